// round 8
// baseline (speedup 1.0000x reference)
#include <cuda_runtime.h>
#include <cstdint>

#define NN 100000
#define EE 1600000
#define CC 128
#define EPS_ 1e-5f
#define NBLK ((NN + 255) / 256)   // 391

// ---------------- scratch (static device globals; no allocation) ----------------
__device__ __align__(16) float g_h[(size_t)NN * CC];     // GEMM output / message features
__device__ __align__(16) float g_agg[(size_t)NN * CC];   // aggregation accumulator
__device__ __align__(16) float g_x1[(size_t)NN * CC];    // x after first block
__device__ float g_dinv[NN];
__device__ float g_as[NN];
__device__ float g_ad[NN];
__device__ float g_stats[2 * CC];
__device__ int g_is64;
// CSR by destination (self-loops NOT stored; handled analytically)
__device__ int g_degc[NN];
__device__ int g_rowstart[NN];
__device__ int g_cur[NN];
__device__ int g_bsum[NBLK + 1];
__device__ int g_boff[NBLK + 1];
__device__ int g_csrc[EE];

// ---------------- edges dtype detection ----------------
__global__ void detect_dtype(const int* __restrict__ e32) {
    __shared__ int ok[256];
    int t = threadIdx.x;
    int all0 = 1;
#pragma unroll
    for (int i = 0; i < 2; i++) {
        int idx = 2 * (t + i * 256) + 1;
        if (e32[idx] != 0) all0 = 0;
    }
    ok[t] = all0;
    __syncthreads();
    for (int s = 128; s; s >>= 1) {
        if (t < s) ok[t] &= ok[t + s];
        __syncthreads();
    }
    if (t == 0) g_is64 = ok[0];
}

__device__ __forceinline__ int edge_src(const int* __restrict__ e32, int t) {
    return g_is64 ? e32[2 * t] : e32[t];
}
__device__ __forceinline__ int edge_dst(const int* __restrict__ e32, int t) {
    return g_is64 ? e32[2 * (EE + t)] : e32[EE + t];
}

// ---------------- CSR build ----------------
__global__ void zero_counts() {
    int i = blockIdx.x * blockDim.x + threadIdx.x;
    if (i < NN) g_degc[i] = 0;
}

__global__ void count_deg_kernel(const int* __restrict__ e32) {
    int t = blockIdx.x * blockDim.x + threadIdx.x;
    if (t < EE) atomicAdd(&g_degc[edge_dst(e32, t)], 1);
}

__global__ void dinv_kernel() {
    int i = blockIdx.x * blockDim.x + threadIdx.x;
    if (i < NN) g_dinv[i] = rsqrtf((float)(g_degc[i] + 1));
}

__global__ void scan1() {
    __shared__ int sm[256];
    int b = blockIdx.x, t = threadIdx.x;
    int idx = b * 256 + t;
    int v = (idx < NN) ? g_degc[idx] : 0;
    sm[t] = v;
    __syncthreads();
    for (int o = 1; o < 256; o <<= 1) {
        int add = (t >= o) ? sm[t - o] : 0;
        __syncthreads();
        sm[t] += add;
        __syncthreads();
    }
    if (idx < NN) g_rowstart[idx] = sm[t] - v;
    if (t == 255) g_bsum[b] = sm[255];
}

__global__ void scan2() {
    __shared__ int sm[512];
    int t = threadIdx.x;
    int v = (t < NBLK) ? g_bsum[t] : 0;
    sm[t] = v;
    __syncthreads();
    for (int o = 1; o < 512; o <<= 1) {
        int add = (t >= o) ? sm[t - o] : 0;
        __syncthreads();
        sm[t] += add;
        __syncthreads();
    }
    if (t < NBLK) g_boff[t] = sm[t] - v;
}

__global__ void scan3() {
    int idx = blockIdx.x * blockDim.x + threadIdx.x;
    if (idx < NN) {
        g_rowstart[idx] += g_boff[blockIdx.x];
        g_cur[idx] = 0;
    }
}

__global__ void fill_csr(const int* __restrict__ e32) {
    int t = blockIdx.x * blockDim.x + threadIdx.x;
    if (t >= EE) return;
    int s = edge_src(e32, t);
    int d = edge_dst(e32, t);
    int pos = g_rowstart[d] + atomicAdd(&g_cur[d], 1);
    g_csrc[pos] = s;
}

// ---------------- TF32 split-precision GEMM: g_h = X @ W ----------------
// Block: 128 rows x 128 cols (full width). 256 threads = 8 warps (2 m x 4 n).
// K chunked by 16. 3xTF32: A*B ~= Ahi*Bhi + Alo*Bhi + Ahi*Blo.
#define MMA_TF32(c, a, b) \
    asm volatile("mma.sync.aligned.m16n8k8.row.col.f32.tf32.tf32.f32 " \
                 "{%0,%1,%2,%3},{%4,%5,%6,%7},{%8,%9},{%0,%1,%2,%3};" \
                 : "+f"((c)[0]), "+f"((c)[1]), "+f"((c)[2]), "+f"((c)[3]) \
                 : "r"((a)[0]), "r"((a)[1]), "r"((a)[2]), "r"((a)[3]), \
                   "r"((b)[0]), "r"((b)[1]))

__device__ __forceinline__ void tf32_split(float v, unsigned& hi, unsigned& lo) {
    asm("cvt.rna.tf32.f32 %0, %1;" : "=r"(hi) : "f"(v));
    float rem = v - __uint_as_float(hi);
    asm("cvt.rna.tf32.f32 %0, %1;" : "=r"(lo) : "f"(rem));
}

template <bool FROM_X1>
__device__ __forceinline__ void gemm_tf32_body(const float* __restrict__ Xext,
                                               const float* __restrict__ W) {
    // fragment-order smem: A[(mt*2+ks)*32+lane] float4 ; B[(nt*2+ks)*32+lane] float2
    __shared__ unsigned sAhi[2048], sAlo[2048];   // 8 mt * 2 ks * 32 lanes * 4 regs
    __shared__ unsigned sBhi[2048], sBlo[2048];   // 16 nt * 2 ks * 32 lanes * 2 regs
    const float* X = FROM_X1 ? g_x1 : Xext;
    int row0 = blockIdx.x * 128;
    int tid = threadIdx.x;
    int w = tid >> 5, lane = tid & 31;
    int wm = w & 1, wn = w >> 1;

    float acc[4][4][4];
#pragma unroll
    for (int mt = 0; mt < 4; mt++)
#pragma unroll
        for (int nt = 0; nt < 4; nt++)
#pragma unroll
            for (int c = 0; c < 4; c++) acc[mt][nt][c] = 0.f;

    for (int kt = 0; kt < 128; kt += 16) {
        // ---- load X chunk [128 rows x 16 k] into A fragment order ----
#pragma unroll
        for (int i = 0; i < 2; i++) {
            int idx = tid + i * 256;          // 0..511
            int r = idx >> 2;                 // 0..127
            int k4 = idx & 3;                 // 0..3 (float4 within 16 k)
            int gr = row0 + r;
            float4 v = (gr < NN) ? ((const float4*)(X + (size_t)gr * 128 + kt))[k4]
                                 : make_float4(0.f, 0.f, 0.f, 0.f);
            int mt = r >> 4, rr = r & 15;
            float vals[4] = {v.x, v.y, v.z, v.w};
#pragma unroll
            for (int e = 0; e < 4; e++) {
                int c = k4 * 4 + e;           // 0..15
                int ks = c >> 3, cc = c & 7;
                int ln = (rr & 7) * 4 + (cc & 3);
                int rg = (rr >> 3) | ((cc >> 2) << 1);
                unsigned hi, lo;
                tf32_split(vals[e], hi, lo);
                int slot = ((mt * 2 + ks) * 32 + ln) * 4 + rg;
                sAhi[slot] = hi;
                sAlo[slot] = lo;
            }
        }
        // ---- load W chunk [16 k x 128 n] into B fragment order ----
#pragma unroll
        for (int i = 0; i < 2; i++) {
            int idx = tid + i * 256;          // 0..511
            int kr = idx >> 5;                // 0..15
            int n4 = idx & 31;
            float4 v = ((const float4*)(W + (size_t)(kt + kr) * 128))[n4];
            int ks = kr >> 3, k_ = kr & 7;
            float vals[4] = {v.x, v.y, v.z, v.w};
#pragma unroll
            for (int e = 0; e < 4; e++) {
                int n = n4 * 4 + e;
                int nt = n >> 3, n_ = n & 7;
                int ln = n_ * 4 + (k_ & 3);
                int rg = k_ >> 2;
                unsigned hi, lo;
                tf32_split(vals[e], hi, lo);
                int slot = ((nt * 2 + ks) * 32 + ln) * 2 + rg;
                sBhi[slot] = hi;
                sBlo[slot] = lo;
            }
        }
        __syncthreads();

#pragma unroll
        for (int ks = 0; ks < 2; ks++) {
            unsigned ahi[4][4], alo[4][4], bhi[4][2], blo[4][2];
#pragma unroll
            for (int mt = 0; mt < 4; mt++) {
                int mtg = wm * 4 + mt;
                int base = ((mtg * 2 + ks) * 32 + lane);
                *(uint4*)ahi[mt] = ((const uint4*)sAhi)[base];
                *(uint4*)alo[mt] = ((const uint4*)sAlo)[base];
            }
#pragma unroll
            for (int nt = 0; nt < 4; nt++) {
                int ntg = wn * 4 + nt;
                int base = ((ntg * 2 + ks) * 32 + lane);
                *(uint2*)bhi[nt] = ((const uint2*)sBhi)[base];
                *(uint2*)blo[nt] = ((const uint2*)sBlo)[base];
            }
#pragma unroll
            for (int mt = 0; mt < 4; mt++)
#pragma unroll
                for (int nt = 0; nt < 4; nt++) {
                    MMA_TF32(acc[mt][nt], ahi[mt], bhi[nt]);
                    MMA_TF32(acc[mt][nt], alo[mt], bhi[nt]);
                    MMA_TF32(acc[mt][nt], ahi[mt], blo[nt]);
                }
        }
        __syncthreads();
    }

    // ---- store ----
#pragma unroll
    for (int mt = 0; mt < 4; mt++) {
        int r0 = row0 + wm * 64 + mt * 16 + (lane >> 2);
        int r1 = r0 + 8;
#pragma unroll
        for (int nt = 0; nt < 4; nt++) {
            int col = wn * 32 + nt * 8 + (lane & 3) * 2;
            if (r0 < NN)
                *(float2*)(g_h + (size_t)r0 * 128 + col) = make_float2(acc[mt][nt][0], acc[mt][nt][1]);
            if (r1 < NN)
                *(float2*)(g_h + (size_t)r1 * 128 + col) = make_float2(acc[mt][nt][2], acc[mt][nt][3]);
        }
    }
}

__global__ void __launch_bounds__(256) gemm_tf32_A(const float* __restrict__ X,
                                                   const float* __restrict__ W) {
    gemm_tf32_body<false>(X, W);
}
__global__ void __launch_bounds__(256) gemm_tf32_B(const float* __restrict__ W) {
    gemm_tf32_body<true>(nullptr, W);
}

// ---------------- GCN gather: warp per dst node ----------------
__global__ void __launch_bounds__(256) gather_gcn() {
    int d = (blockIdx.x * blockDim.x + threadIdx.x) >> 5;
    if (d >= NN) return;
    int lane = threadIdx.x & 31;
    int beg = g_rowstart[d];
    int num = g_degc[d];
    float dd = g_dinv[d];
    float4 acc = ((const float4*)(g_h + (size_t)d * 128))[lane];
    float w0 = dd * dd;
    acc.x *= w0; acc.y *= w0; acc.z *= w0; acc.w *= w0;
    for (int j = beg; j < beg + num; j++) {
        int s = g_csrc[j];
        float w = g_dinv[s] * dd;
        float4 v = ((const float4*)(g_h + (size_t)s * 128))[lane];
        acc.x = fmaf(v.x, w, acc.x);
        acc.y = fmaf(v.y, w, acc.y);
        acc.z = fmaf(v.z, w, acc.z);
        acc.w = fmaf(v.w, w, acc.w);
    }
    ((float4*)(g_agg + (size_t)d * 128))[lane] = acc;
}

// ---------------- column stats ----------------
__global__ void zero_stats() {
    int i = threadIdx.x;
    if (i < 2 * CC) g_stats[i] = 0.f;
}

__global__ void colstats(const float* __restrict__ bias) {
    __shared__ float s1[256], s2[256];
    int c = threadIdx.x & 127;
    int half = threadIdx.x >> 7;
    float b = bias[c];
    float acc = 0.f, acc2 = 0.f;
    for (int r = blockIdx.x * 2 + half; r < NN; r += gridDim.x * 2) {
        float t = g_agg[(size_t)r * 128 + c] + b;
        acc += t;
        acc2 += t * t;
    }
    s1[threadIdx.x] = acc;
    s2[threadIdx.x] = acc2;
    __syncthreads();
    if (half == 0) {
        atomicAdd(&g_stats[c], s1[c] + s1[c + 128]);
        atomicAdd(&g_stats[128 + c], s2[c] + s2[c + 128]);
    }
}

// ---------------- finalize: GraphNorm + LeakyReLU + residual ----------------
template <bool PHASE_B>
__device__ __forceinline__ void finalize_body(const float* __restrict__ xin_ext,
                                              const float* __restrict__ bias,
                                              const float* __restrict__ gw,
                                              const float* __restrict__ gb,
                                              const float* __restrict__ gms,
                                              float* __restrict__ xout_ext) {
    int idx = blockIdx.x * blockDim.x + threadIdx.x;
    if (idx >= NN * CC) return;
    int c = idx & 127;
    float t = g_agg[idx] + bias[c];
    const float invn = 1.0f / (float)NN;
    float mean = g_stats[c] * invn;
    float a = gms[c] * mean;
    float var = g_stats[128 + c] * invn - 2.f * a * mean + a * a;
    float y = gw[c] * (t - a) * rsqrtf(var + EPS_) + gb[c];
    y = (y >= 0.f) ? y : 0.01f * y;
    float xv = PHASE_B ? g_x1[idx] : xin_ext[idx];
    float r = xv + y;
    if (PHASE_B) xout_ext[idx] = r;
    else g_x1[idx] = r;
}

__global__ void finalize_A(const float* __restrict__ xin, const float* __restrict__ bias,
                           const float* __restrict__ gw, const float* __restrict__ gb,
                           const float* __restrict__ gms) {
    finalize_body<false>(xin, bias, gw, gb, gms, nullptr);
}
__global__ void finalize_B(const float* __restrict__ bias, const float* __restrict__ gw,
                           const float* __restrict__ gb, const float* __restrict__ gms,
                           float* __restrict__ xout) {
    finalize_body<true>(nullptr, bias, gw, gb, gms, xout);
}

// ---------------- GAT attention dots: warp per node ----------------
__global__ void attndot(const float* __restrict__ att_src, const float* __restrict__ att_dst) {
    int warp = (blockIdx.x * blockDim.x + threadIdx.x) >> 5;
    if (warp >= NN) return;
    int lane = threadIdx.x & 31;
    float4 hv = ((const float4*)(g_h + (size_t)warp * 128))[lane];
    float4 av = ((const float4*)att_src)[lane];
    float4 dv = ((const float4*)att_dst)[lane];
    float ps = hv.x * av.x + hv.y * av.y + hv.z * av.z + hv.w * av.w;
    float pd = hv.x * dv.x + hv.y * dv.y + hv.z * dv.z + hv.w * dv.w;
#pragma unroll
    for (int o = 16; o; o >>= 1) {
        ps += __shfl_xor_sync(0xffffffffu, ps, o);
        pd += __shfl_xor_sync(0xffffffffu, pd, o);
    }
    if (lane == 0) {
        g_as[warp] = ps;
        g_ad[warp] = pd;
    }
}

// ---------------- GAT gather (fused softmax): warp per dst node ----------------
__global__ void __launch_bounds__(256) gather_gat() {
    int d = (blockIdx.x * blockDim.x + threadIdx.x) >> 5;
    if (d >= NN) return;
    int lane = threadIdx.x & 31;
    int beg = g_rowstart[d];
    int end = beg + g_degc[d];
    float add = g_ad[d];
    float es = g_as[d] + add;
    es = (es >= 0.f) ? es : 0.2f * es;

    float m = es;
    for (int j = beg + lane; j < end; j += 32) {
        float e = g_as[g_csrc[j]] + add;
        e = (e >= 0.f) ? e : 0.2f * e;
        m = fmaxf(m, e);
    }
#pragma unroll
    for (int o = 16; o; o >>= 1) m = fmaxf(m, __shfl_xor_sync(0xffffffffu, m, o));

    float den = __expf(es - m);
    {
        float part = 0.f;
        for (int j = beg + lane; j < end; j += 32) {
            float e = g_as[g_csrc[j]] + add;
            e = (e >= 0.f) ? e : 0.2f * e;
            part += __expf(e - m);
        }
#pragma unroll
        for (int o = 16; o; o >>= 1) part += __shfl_xor_sync(0xffffffffu, part, o);
        den += part;
    }
    float rden = 1.0f / den;

    float4 acc = ((const float4*)(g_h + (size_t)d * 128))[lane];
    float ws = __expf(es - m);
    acc.x *= ws; acc.y *= ws; acc.z *= ws; acc.w *= ws;
    for (int j = beg; j < end; j++) {
        int s = g_csrc[j];
        float e = g_as[s] + add;
        e = (e >= 0.f) ? e : 0.2f * e;
        float w = __expf(e - m);
        float4 v = ((const float4*)(g_h + (size_t)s * 128))[lane];
        acc.x = fmaf(v.x, w, acc.x);
        acc.y = fmaf(v.y, w, acc.y);
        acc.z = fmaf(v.z, w, acc.z);
        acc.w = fmaf(v.w, w, acc.w);
    }
    acc.x *= rden; acc.y *= rden; acc.z *= rden; acc.w *= rden;
    ((float4*)(g_agg + (size_t)d * 128))[lane] = acc;
}

// ---------------- launch ----------------
extern "C" void kernel_launch(void* const* d_in, const int* in_sizes, int n_in,
                              void* d_out, int out_size) {
    const float* x = (const float*)d_in[0];
    const int* e32 = (const int*)d_in[1];
    const float* W1 = (const float*)d_in[2];
    const float* b1 = (const float*)d_in[3];
    const float* gn_w = (const float*)d_in[4];
    const float* gn_b = (const float*)d_in[5];
    const float* gn_ms = (const float*)d_in[6];
    const float* Wg = (const float*)d_in[7];
    const float* bg = (const float*)d_in[8];
    const float* att_src = (const float*)d_in[9];
    const float* att_dst = (const float*)d_in[10];
    float* out = (float*)d_out;

    const int TPB = 256;
    const int nb_node = NBLK;
    const int nb_edge = (EE + TPB - 1) / TPB;
    const int nb_warp_node = (NN * 32 + TPB - 1) / TPB;
    const int nb_elem = (NN * CC + TPB - 1) / TPB;
    const int gemm_blocks = (NN + 127) / 128;

    detect_dtype<<<1, 256>>>(e32);

    // ---- CSR build ----
    zero_counts<<<nb_node, TPB>>>();
    count_deg_kernel<<<nb_edge, TPB>>>(e32);
    dinv_kernel<<<nb_node, TPB>>>();
    scan1<<<nb_node, 256>>>();
    scan2<<<1, 512>>>();
    scan3<<<nb_node, 256>>>();
    fill_csr<<<nb_edge, TPB>>>(e32);

    // ---- Phase A: GCN ----
    gemm_tf32_A<<<gemm_blocks, 256>>>(x, W1);
    gather_gcn<<<nb_warp_node, TPB>>>();
    zero_stats<<<1, 256>>>();
    colstats<<<512, 256>>>(b1);
    finalize_A<<<nb_elem, TPB>>>(x, b1, gn_w, gn_b, gn_ms);

    // ---- Phase B: GAT ----
    gemm_tf32_B<<<gemm_blocks, 256>>>(Wg);
    attndot<<<nb_warp_node, TPB>>>(att_src, att_dst);
    gather_gat<<<nb_warp_node, TPB>>>();
    zero_stats<<<1, 256>>>();
    colstats<<<512, 256>>>(bg);
    finalize_B<<<nb_elem, TPB>>>(bg, gn_w, gn_b, gn_ms, out);
}

// round 9
// speedup vs baseline: 1.3332x; 1.3332x over previous
#include <cuda_runtime.h>
#include <cstdint>

#define NN 100000
#define EE 1600000
#define CC 128
#define EPS_ 1e-5f
#define NBLK ((NN + 255) / 256)   // 391

// ---------------- scratch (static device globals; no allocation) ----------------
__device__ __align__(16) float g_h[(size_t)NN * CC];
__device__ __align__(16) float g_agg[(size_t)NN * CC];
__device__ __align__(16) float g_x1[(size_t)NN * CC];
__device__ float g_dinv[NN];
__device__ float g_as[NN];
__device__ float g_ad[NN];
__device__ float g_stats[2 * CC];
__device__ int g_is64;
__device__ int g_degc[NN];
__device__ int g_rowstart[NN];
__device__ int g_cur[NN];
__device__ int g_bsum[NBLK + 1];
__device__ int g_boff[NBLK + 1];
__device__ int g_csrc[EE];
// W pre-split into m16n8k8 B-fragment order: slot = ((kc*16+nt)*32+lane)*2+rg
__device__ __align__(16) unsigned g_Whi[16384];
__device__ __align__(16) unsigned g_Wlo[16384];

// ---------------- edges dtype detection ----------------
__global__ void detect_dtype(const int* __restrict__ e32) {
    __shared__ int ok[256];
    int t = threadIdx.x;
    int all0 = 1;
#pragma unroll
    for (int i = 0; i < 2; i++) {
        int idx = 2 * (t + i * 256) + 1;
        if (e32[idx] != 0) all0 = 0;
    }
    ok[t] = all0;
    __syncthreads();
    for (int s = 128; s; s >>= 1) {
        if (t < s) ok[t] &= ok[t + s];
        __syncthreads();
    }
    if (t == 0) g_is64 = ok[0];
}

__device__ __forceinline__ int edge_src(const int* __restrict__ e32, int t) {
    return g_is64 ? e32[2 * t] : e32[t];
}
__device__ __forceinline__ int edge_dst(const int* __restrict__ e32, int t) {
    return g_is64 ? e32[2 * (EE + t)] : e32[EE + t];
}

// ---------------- CSR build ----------------
__global__ void zero_counts() {
    int i = blockIdx.x * blockDim.x + threadIdx.x;
    if (i < NN) g_degc[i] = 0;
}

__global__ void count_deg_kernel(const int* __restrict__ e32) {
    int t = blockIdx.x * blockDim.x + threadIdx.x;
    if (t < EE) atomicAdd(&g_degc[edge_dst(e32, t)], 1);
}

__global__ void dinv_kernel() {
    int i = blockIdx.x * blockDim.x + threadIdx.x;
    if (i < NN) g_dinv[i] = rsqrtf((float)(g_degc[i] + 1));
}

__global__ void scan1() {
    __shared__ int sm[256];
    int b = blockIdx.x, t = threadIdx.x;
    int idx = b * 256 + t;
    int v = (idx < NN) ? g_degc[idx] : 0;
    sm[t] = v;
    __syncthreads();
    for (int o = 1; o < 256; o <<= 1) {
        int add = (t >= o) ? sm[t - o] : 0;
        __syncthreads();
        sm[t] += add;
        __syncthreads();
    }
    if (idx < NN) g_rowstart[idx] = sm[t] - v;
    if (t == 255) g_bsum[b] = sm[255];
}

__global__ void scan2() {
    __shared__ int sm[512];
    int t = threadIdx.x;
    int v = (t < NBLK) ? g_bsum[t] : 0;
    sm[t] = v;
    __syncthreads();
    for (int o = 1; o < 512; o <<= 1) {
        int add = (t >= o) ? sm[t - o] : 0;
        __syncthreads();
        sm[t] += add;
        __syncthreads();
    }
    if (t < NBLK) g_boff[t] = sm[t] - v;
}

__global__ void scan3() {
    int idx = blockIdx.x * blockDim.x + threadIdx.x;
    if (idx < NN) {
        g_rowstart[idx] += g_boff[blockIdx.x];
        g_cur[idx] = 0;
    }
}

__global__ void fill_csr(const int* __restrict__ e32) {
    int t = blockIdx.x * blockDim.x + threadIdx.x;
    if (t >= EE) return;
    int s = edge_src(e32, t);
    int d = edge_dst(e32, t);
    int pos = g_rowstart[d] + atomicAdd(&g_cur[d], 1);
    g_csrc[pos] = s;
}

// ---------------- TF32 GEMM ----------------
#define MMA_TF32(c, a, b) \
    asm volatile("mma.sync.aligned.m16n8k8.row.col.f32.tf32.tf32.f32 " \
                 "{%0,%1,%2,%3},{%4,%5,%6,%7},{%8,%9},{%0,%1,%2,%3};" \
                 : "+f"((c)[0]), "+f"((c)[1]), "+f"((c)[2]), "+f"((c)[3]) \
                 : "r"((a)[0]), "r"((a)[1]), "r"((a)[2]), "r"((a)[3]), \
                   "r"((b)[0]), "r"((b)[1]))

__device__ __forceinline__ void tf32_split(float v, unsigned& hi, unsigned& lo) {
    asm("cvt.rna.tf32.f32 %0, %1;" : "=r"(hi) : "f"(v));
    float rem = v - __uint_as_float(hi);
    asm("cvt.rna.tf32.f32 %0, %1;" : "=r"(lo) : "f"(rem));
}

// Pre-split W [128x128] into B-fragment order (hi/lo). 16384 slots.
__global__ void split_W(const float* __restrict__ W) {
    int slot = blockIdx.x * 256 + threadIdx.x;   // 0..16383
    int rg = slot & 1;
    int lane = (slot >> 1) & 31;
    int nt = (slot >> 6) & 15;
    int kc = slot >> 10;
    int k = kc * 8 + rg * 4 + (lane & 3);
    int n = nt * 8 + (lane >> 2);
    unsigned hi, lo;
    tf32_split(W[k * 128 + n], hi, lo);
    g_Whi[slot] = hi;
    g_Wlo[slot] = lo;
}

// GEMM: g_h[128-row tile] = X @ W. 256 thr = 8 warps (2 m x 4 n). No smem.
template <bool FROM_X1>
__device__ __forceinline__ void gemm_tf32_body(const float* __restrict__ Xext) {
    const float* X = FROM_X1 ? g_x1 : Xext;
    int row0 = blockIdx.x * 128;
    int tid = threadIdx.x;
    int w = tid >> 5, lane = tid & 31;
    int wm = w & 1, wn = w >> 1;
    int grp = lane >> 2, four = lane & 3;

    float acc[4][4][4];
#pragma unroll
    for (int mt = 0; mt < 4; mt++)
#pragma unroll
        for (int nt = 0; nt < 4; nt++)
#pragma unroll
            for (int c = 0; c < 4; c++) acc[mt][nt][c] = 0.f;

    // row indices per mt (row r and r+8)
    int rbase = row0 + wm * 64 + grp;

#pragma unroll 4
    for (int kc = 0; kc < 16; kc++) {
        int col = kc * 8 + four;
        // B fragments for this warp's 4 n-tiles
        unsigned bhi[4][2], blo[4][2];
#pragma unroll
        for (int nt = 0; nt < 4; nt++) {
            int ntg = wn * 4 + nt;
            int base = (kc * 16 + ntg) * 32 + lane;
            *(uint2*)bhi[nt] = ((const uint2*)g_Whi)[base];
            *(uint2*)blo[nt] = ((const uint2*)g_Wlo)[base];
        }
        // A fragments per mt, loaded direct from global, split in regs
#pragma unroll
        for (int mt = 0; mt < 4; mt++) {
            int r0 = rbase + mt * 16;
            int r1 = r0 + 8;
            float f0 = (r0 < NN) ? X[(size_t)r0 * 128 + col] : 0.f;
            float f1 = (r1 < NN) ? X[(size_t)r1 * 128 + col] : 0.f;
            float f2 = (r0 < NN) ? X[(size_t)r0 * 128 + col + 4] : 0.f;
            float f3 = (r1 < NN) ? X[(size_t)r1 * 128 + col + 4] : 0.f;
            unsigned ahi[4], alo[4];
            tf32_split(f0, ahi[0], alo[0]);
            tf32_split(f1, ahi[1], alo[1]);
            tf32_split(f2, ahi[2], alo[2]);
            tf32_split(f3, ahi[3], alo[3]);
#pragma unroll
            for (int nt = 0; nt < 4; nt++) {
                MMA_TF32(acc[mt][nt], ahi, bhi[nt]);
                MMA_TF32(acc[mt][nt], alo, bhi[nt]);
                MMA_TF32(acc[mt][nt], ahi, blo[nt]);
            }
        }
    }

    // store
#pragma unroll
    for (int mt = 0; mt < 4; mt++) {
        int r0 = rbase + mt * 16;
        int r1 = r0 + 8;
#pragma unroll
        for (int nt = 0; nt < 4; nt++) {
            int coln = wn * 32 + nt * 8 + four * 2;
            if (r0 < NN)
                *(float2*)(g_h + (size_t)r0 * 128 + coln) = make_float2(acc[mt][nt][0], acc[mt][nt][1]);
            if (r1 < NN)
                *(float2*)(g_h + (size_t)r1 * 128 + coln) = make_float2(acc[mt][nt][2], acc[mt][nt][3]);
        }
    }
}

__global__ void __launch_bounds__(256) gemm_tf32_A(const float* __restrict__ X) {
    gemm_tf32_body<false>(X);
}
__global__ void __launch_bounds__(256) gemm_tf32_B() {
    gemm_tf32_body<true>(nullptr);
}

// ---------------- GCN gather ----------------
__global__ void __launch_bounds__(256) gather_gcn() {
    int d = (blockIdx.x * blockDim.x + threadIdx.x) >> 5;
    if (d >= NN) return;
    int lane = threadIdx.x & 31;
    int beg = g_rowstart[d];
    int num = g_degc[d];
    float dd = g_dinv[d];
    float4 acc = ((const float4*)(g_h + (size_t)d * 128))[lane];
    float w0 = dd * dd;
    acc.x *= w0; acc.y *= w0; acc.z *= w0; acc.w *= w0;
    for (int j = beg; j < beg + num; j++) {
        int s = g_csrc[j];
        float w = g_dinv[s] * dd;
        float4 v = ((const float4*)(g_h + (size_t)s * 128))[lane];
        acc.x = fmaf(v.x, w, acc.x);
        acc.y = fmaf(v.y, w, acc.y);
        acc.z = fmaf(v.z, w, acc.z);
        acc.w = fmaf(v.w, w, acc.w);
    }
    ((float4*)(g_agg + (size_t)d * 128))[lane] = acc;
}

// ---------------- column stats ----------------
__global__ void zero_stats() {
    int i = threadIdx.x;
    if (i < 2 * CC) g_stats[i] = 0.f;
}

__global__ void colstats(const float* __restrict__ bias) {
    __shared__ float s1[256], s2[256];
    int c = threadIdx.x & 127;
    int half = threadIdx.x >> 7;
    float b = bias[c];
    float acc = 0.f, acc2 = 0.f;
    for (int r = blockIdx.x * 2 + half; r < NN; r += gridDim.x * 2) {
        float t = g_agg[(size_t)r * 128 + c] + b;
        acc += t;
        acc2 += t * t;
    }
    s1[threadIdx.x] = acc;
    s2[threadIdx.x] = acc2;
    __syncthreads();
    if (half == 0) {
        atomicAdd(&g_stats[c], s1[c] + s1[c + 128]);
        atomicAdd(&g_stats[128 + c], s2[c] + s2[c + 128]);
    }
}

// ---------------- finalize ----------------
template <bool PHASE_B>
__device__ __forceinline__ void finalize_body(const float* __restrict__ xin_ext,
                                              const float* __restrict__ bias,
                                              const float* __restrict__ gw,
                                              const float* __restrict__ gb,
                                              const float* __restrict__ gms,
                                              float* __restrict__ xout_ext) {
    int idx = blockIdx.x * blockDim.x + threadIdx.x;
    if (idx >= NN * CC) return;
    int c = idx & 127;
    float t = g_agg[idx] + bias[c];
    const float invn = 1.0f / (float)NN;
    float mean = g_stats[c] * invn;
    float a = gms[c] * mean;
    float var = g_stats[128 + c] * invn - 2.f * a * mean + a * a;
    float y = gw[c] * (t - a) * rsqrtf(var + EPS_) + gb[c];
    y = (y >= 0.f) ? y : 0.01f * y;
    float xv = PHASE_B ? g_x1[idx] : xin_ext[idx];
    float r = xv + y;
    if (PHASE_B) xout_ext[idx] = r;
    else g_x1[idx] = r;
}

__global__ void finalize_A(const float* __restrict__ xin, const float* __restrict__ bias,
                           const float* __restrict__ gw, const float* __restrict__ gb,
                           const float* __restrict__ gms) {
    finalize_body<false>(xin, bias, gw, gb, gms, nullptr);
}
__global__ void finalize_B(const float* __restrict__ bias, const float* __restrict__ gw,
                           const float* __restrict__ gb, const float* __restrict__ gms,
                           float* __restrict__ xout) {
    finalize_body<true>(nullptr, bias, gw, gb, gms, xout);
}

// ---------------- GAT attention dots ----------------
__global__ void attndot(const float* __restrict__ att_src, const float* __restrict__ att_dst) {
    int warp = (blockIdx.x * blockDim.x + threadIdx.x) >> 5;
    if (warp >= NN) return;
    int lane = threadIdx.x & 31;
    float4 hv = ((const float4*)(g_h + (size_t)warp * 128))[lane];
    float4 av = ((const float4*)att_src)[lane];
    float4 dv = ((const float4*)att_dst)[lane];
    float ps = hv.x * av.x + hv.y * av.y + hv.z * av.z + hv.w * av.w;
    float pd = hv.x * dv.x + hv.y * dv.y + hv.z * dv.z + hv.w * dv.w;
#pragma unroll
    for (int o = 16; o; o >>= 1) {
        ps += __shfl_xor_sync(0xffffffffu, ps, o);
        pd += __shfl_xor_sync(0xffffffffu, pd, o);
    }
    if (lane == 0) {
        g_as[warp] = ps;
        g_ad[warp] = pd;
    }
}

// ---------------- GAT gather (fused softmax) ----------------
__global__ void __launch_bounds__(256) gather_gat() {
    int d = (blockIdx.x * blockDim.x + threadIdx.x) >> 5;
    if (d >= NN) return;
    int lane = threadIdx.x & 31;
    int beg = g_rowstart[d];
    int end = beg + g_degc[d];
    float add = g_ad[d];
    float es = g_as[d] + add;
    es = (es >= 0.f) ? es : 0.2f * es;

    float m = es;
    for (int j = beg + lane; j < end; j += 32) {
        float e = g_as[g_csrc[j]] + add;
        e = (e >= 0.f) ? e : 0.2f * e;
        m = fmaxf(m, e);
    }
#pragma unroll
    for (int o = 16; o; o >>= 1) m = fmaxf(m, __shfl_xor_sync(0xffffffffu, m, o));

    float den = __expf(es - m);
    {
        float part = 0.f;
        for (int j = beg + lane; j < end; j += 32) {
            float e = g_as[g_csrc[j]] + add;
            e = (e >= 0.f) ? e : 0.2f * e;
            part += __expf(e - m);
        }
#pragma unroll
        for (int o = 16; o; o >>= 1) part += __shfl_xor_sync(0xffffffffu, part, o);
        den += part;
    }
    float rden = 1.0f / den;

    float4 acc = ((const float4*)(g_h + (size_t)d * 128))[lane];
    float ws = __expf(es - m);
    acc.x *= ws; acc.y *= ws; acc.z *= ws; acc.w *= ws;
    for (int j = beg; j < end; j++) {
        int s = g_csrc[j];
        float e = g_as[s] + add;
        e = (e >= 0.f) ? e : 0.2f * e;
        float w = __expf(e - m);
        float4 v = ((const float4*)(g_h + (size_t)s * 128))[lane];
        acc.x = fmaf(v.x, w, acc.x);
        acc.y = fmaf(v.y, w, acc.y);
        acc.z = fmaf(v.z, w, acc.z);
        acc.w = fmaf(v.w, w, acc.w);
    }
    acc.x *= rden; acc.y *= rden; acc.z *= rden; acc.w *= rden;
    ((float4*)(g_agg + (size_t)d * 128))[lane] = acc;
}

// ---------------- launch ----------------
extern "C" void kernel_launch(void* const* d_in, const int* in_sizes, int n_in,
                              void* d_out, int out_size) {
    const float* x = (const float*)d_in[0];
    const int* e32 = (const int*)d_in[1];
    const float* W1 = (const float*)d_in[2];
    const float* b1 = (const float*)d_in[3];
    const float* gn_w = (const float*)d_in[4];
    const float* gn_b = (const float*)d_in[5];
    const float* gn_ms = (const float*)d_in[6];
    const float* Wg = (const float*)d_in[7];
    const float* bg = (const float*)d_in[8];
    const float* att_src = (const float*)d_in[9];
    const float* att_dst = (const float*)d_in[10];
    float* out = (float*)d_out;

    const int TPB = 256;
    const int nb_node = NBLK;
    const int nb_edge = (EE + TPB - 1) / TPB;
    const int nb_warp_node = (NN * 32 + TPB - 1) / TPB;
    const int nb_elem = (NN * CC + TPB - 1) / TPB;
    const int gemm_blocks = (NN + 127) / 128;

    detect_dtype<<<1, 256>>>(e32);

    // ---- CSR build ----
    zero_counts<<<nb_node, TPB>>>();
    count_deg_kernel<<<nb_edge, TPB>>>(e32);
    dinv_kernel<<<nb_node, TPB>>>();
    scan1<<<nb_node, 256>>>();
    scan2<<<1, 512>>>();
    scan3<<<nb_node, 256>>>();
    fill_csr<<<nb_edge, TPB>>>(e32);

    // ---- Phase A: GCN ----
    split_W<<<64, 256>>>(W1);
    gemm_tf32_A<<<gemm_blocks, 256>>>(x);
    gather_gcn<<<nb_warp_node, TPB>>>();
    zero_stats<<<1, 256>>>();
    colstats<<<512, 256>>>(b1);
    finalize_A<<<nb_elem, TPB>>>(x, b1, gn_w, gn_b, gn_ms);

    // ---- Phase B: GAT ----
    split_W<<<64, 256>>>(Wg);
    gemm_tf32_B<<<gemm_blocks, 256>>>();
    attndot<<<nb_warp_node, TPB>>>(att_src, att_dst);
    gather_gat<<<nb_warp_node, TPB>>>();
    zero_stats<<<1, 256>>>();
    colstats<<<512, 256>>>(bg);
    finalize_B<<<nb_elem, TPB>>>(bg, gn_w, gn_b, gn_ms, out);
}

// round 12
// speedup vs baseline: 1.3989x; 1.0493x over previous
#include <cuda_runtime.h>
#include <cstdint>

#define NN 100000
#define EE 1600000
#define CC 128
#define EPS_ 1e-5f
#define NBLK ((NN + 255) / 256)   // 391

// ---------------- scratch ----------------
__device__ __align__(16) float g_h[(size_t)NN * CC];
__device__ __align__(16) float g_agg[(size_t)NN * CC];
__device__ __align__(16) float g_x1[(size_t)NN * CC];
__device__ float g_dinv[NN];
__device__ float g_as[NN];
__device__ float g_ad[NN];
__device__ float g_stats[2 * CC];
__device__ int g_is64;
__device__ int g_degc[NN];
__device__ int g_rowstart[NN];
__device__ int g_cur[NN];
__device__ int g_bsum[NBLK + 1];
__device__ int g_boff[NBLK + 1];
__device__ int g_csrc[EE];
__device__ __align__(16) unsigned g_Whi[16384];
__device__ __align__(16) unsigned g_Wlo[16384];

// ---------------- edges dtype detection ----------------
__global__ void detect_dtype(const int* __restrict__ e32) {
    __shared__ int ok[256];
    int t = threadIdx.x;
    int all0 = 1;
#pragma unroll
    for (int i = 0; i < 2; i++) {
        int idx = 2 * (t + i * 256) + 1;
        if (e32[idx] != 0) all0 = 0;
    }
    ok[t] = all0;
    __syncthreads();
    for (int s = 128; s; s >>= 1) {
        if (t < s) ok[t] &= ok[t + s];
        __syncthreads();
    }
    if (t == 0) g_is64 = ok[0];
}

__device__ __forceinline__ int edge_src(const int* __restrict__ e32, int t) {
    return g_is64 ? e32[2 * t] : e32[t];
}
__device__ __forceinline__ int edge_dst(const int* __restrict__ e32, int t) {
    return g_is64 ? e32[2 * (EE + t)] : e32[EE + t];
}

// ---------------- CSR build ----------------
__global__ void zero_counts() {
    int i = blockIdx.x * blockDim.x + threadIdx.x;
    if (i < NN) g_degc[i] = 0;
}

__global__ void count_deg_kernel(const int* __restrict__ e32) {
    int t = blockIdx.x * blockDim.x + threadIdx.x;
    if (t < EE) atomicAdd(&g_degc[edge_dst(e32, t)], 1);
}

__global__ void dinv_kernel() {
    int i = blockIdx.x * blockDim.x + threadIdx.x;
    if (i < NN) g_dinv[i] = rsqrtf((float)(g_degc[i] + 1));
}

__global__ void scan1() {
    __shared__ int sm[256];
    int b = blockIdx.x, t = threadIdx.x;
    int idx = b * 256 + t;
    int v = (idx < NN) ? g_degc[idx] : 0;
    sm[t] = v;
    __syncthreads();
    for (int o = 1; o < 256; o <<= 1) {
        int add = (t >= o) ? sm[t - o] : 0;
        __syncthreads();
        sm[t] += add;
        __syncthreads();
    }
    if (idx < NN) g_rowstart[idx] = sm[t] - v;
    if (t == 255) g_bsum[b] = sm[255];
}

__global__ void scan2() {
    __shared__ int sm[512];
    int t = threadIdx.x;
    int v = (t < NBLK) ? g_bsum[t] : 0;
    sm[t] = v;
    __syncthreads();
    for (int o = 1; o < 512; o <<= 1) {
        int add = (t >= o) ? sm[t - o] : 0;
        __syncthreads();
        sm[t] += add;
        __syncthreads();
    }
    if (t < NBLK) g_boff[t] = sm[t] - v;
}

__global__ void scan3() {
    int idx = blockIdx.x * blockDim.x + threadIdx.x;
    if (idx < NN) {
        g_rowstart[idx] += g_boff[blockIdx.x];
        g_cur[idx] = 0;
    }
}

__global__ void fill_csr(const int* __restrict__ e32) {
    int t = blockIdx.x * blockDim.x + threadIdx.x;
    if (t >= EE) return;
    int s = edge_src(e32, t);
    int d = edge_dst(e32, t);
    int pos = g_rowstart[d] + atomicAdd(&g_cur[d], 1);
    g_csrc[pos] = s;
}

// ---------------- TF32 GEMM ----------------
#define MMA_TF32(c, a, b) \
    asm volatile("mma.sync.aligned.m16n8k8.row.col.f32.tf32.tf32.f32 " \
                 "{%0,%1,%2,%3},{%4,%5,%6,%7},{%8,%9},{%0,%1,%2,%3};" \
                 : "+f"((c)[0]), "+f"((c)[1]), "+f"((c)[2]), "+f"((c)[3]) \
                 : "r"((a)[0]), "r"((a)[1]), "r"((a)[2]), "r"((a)[3]), \
                   "r"((b)[0]), "r"((b)[1]))

__device__ __forceinline__ void tf32_split(float v, unsigned& hi, unsigned& lo) {
    asm("cvt.rna.tf32.f32 %0, %1;" : "=r"(hi) : "f"(v));
    float rem = v - __uint_as_float(hi);
    asm("cvt.rna.tf32.f32 %0, %1;" : "=r"(lo) : "f"(rem));
}

__global__ void split_W(const float* __restrict__ W) {
    int slot = blockIdx.x * 256 + threadIdx.x;   // 0..16383
    int rg = slot & 1;
    int lane = (slot >> 1) & 31;
    int nt = (slot >> 6) & 15;
    int kc = slot >> 10;
    int k = kc * 8 + rg * 4 + (lane & 3);
    int n = nt * 8 + (lane >> 2);
    unsigned hi, lo;
    tf32_split(W[k * 128 + n], hi, lo);
    g_Whi[slot] = hi;
    g_Wlo[slot] = lo;
}

template <bool FROM_X1>
__device__ __forceinline__ void gemm_tf32_body(const float* __restrict__ Xext) {
    const float* X = FROM_X1 ? g_x1 : Xext;
    int row0 = blockIdx.x * 128;
    int tid = threadIdx.x;
    int w = tid >> 5, lane = tid & 31;
    int wm = w & 1, wn = w >> 1;
    int grp = lane >> 2, four = lane & 3;

    float acc[4][4][4];
#pragma unroll
    for (int mt = 0; mt < 4; mt++)
#pragma unroll
        for (int nt = 0; nt < 4; nt++)
#pragma unroll
            for (int c = 0; c < 4; c++) acc[mt][nt][c] = 0.f;

    int rbase = row0 + wm * 64 + grp;

#pragma unroll 4
    for (int kc = 0; kc < 16; kc++) {
        int col = kc * 8 + four;
        unsigned bhi[4][2], blo[4][2];
#pragma unroll
        for (int nt = 0; nt < 4; nt++) {
            int ntg = wn * 4 + nt;
            int base = (kc * 16 + ntg) * 32 + lane;
            *(uint2*)bhi[nt] = ((const uint2*)g_Whi)[base];
            *(uint2*)blo[nt] = ((const uint2*)g_Wlo)[base];
        }
#pragma unroll
        for (int mt = 0; mt < 4; mt++) {
            int r0 = rbase + mt * 16;
            int r1 = r0 + 8;
            float f0 = (r0 < NN) ? X[(size_t)r0 * 128 + col] : 0.f;
            float f1 = (r1 < NN) ? X[(size_t)r1 * 128 + col] : 0.f;
            float f2 = (r0 < NN) ? X[(size_t)r0 * 128 + col + 4] : 0.f;
            float f3 = (r1 < NN) ? X[(size_t)r1 * 128 + col + 4] : 0.f;
            unsigned ahi[4], alo[4];
            tf32_split(f0, ahi[0], alo[0]);
            tf32_split(f1, ahi[1], alo[1]);
            tf32_split(f2, ahi[2], alo[2]);
            tf32_split(f3, ahi[3], alo[3]);
#pragma unroll
            for (int nt = 0; nt < 4; nt++) {
                MMA_TF32(acc[mt][nt], ahi, bhi[nt]);
                MMA_TF32(acc[mt][nt], alo, bhi[nt]);
                MMA_TF32(acc[mt][nt], ahi, blo[nt]);
            }
        }
    }

#pragma unroll
    for (int mt = 0; mt < 4; mt++) {
        int r0 = rbase + mt * 16;
        int r1 = r0 + 8;
#pragma unroll
        for (int nt = 0; nt < 4; nt++) {
            int coln = wn * 32 + nt * 8 + four * 2;
            if (r0 < NN)
                *(float2*)(g_h + (size_t)r0 * 128 + coln) = make_float2(acc[mt][nt][0], acc[mt][nt][1]);
            if (r1 < NN)
                *(float2*)(g_h + (size_t)r1 * 128 + coln) = make_float2(acc[mt][nt][2], acc[mt][nt][3]);
        }
    }
}

__global__ void __launch_bounds__(256) gemm_tf32_A(const float* __restrict__ X) {
    gemm_tf32_body<false>(X);
}
__global__ void __launch_bounds__(256) gemm_tf32_B() {
    gemm_tf32_body<true>(nullptr);
}

// ---------------- GCN gather: warp per dst, lane-cached edges ----------------
__global__ void __launch_bounds__(256) gather_gcn() {
    int d = (blockIdx.x * blockDim.x + threadIdx.x) >> 5;
    if (d >= NN) return;
    int lane = threadIdx.x & 31;
    int beg = g_rowstart[d];
    int deg = g_degc[d];
    float dd = g_dinv[d];

    // lane-cached first 32 edges: coalesced csrc load + per-edge weight once
    int s_l = (lane < deg) ? g_csrc[beg + lane] : 0;
    float w_l = (lane < deg) ? g_dinv[s_l] * dd : 0.f;

    float4 acc = ((const float4*)(g_h + (size_t)d * 128))[lane];
    float w0 = dd * dd;
    acc.x *= w0; acc.y *= w0; acc.z *= w0; acc.w *= w0;

    int n32 = deg < 32 ? deg : 32;
    for (int j = 0; j < n32; j++) {
        int s = __shfl_sync(0xffffffffu, s_l, j);
        float w = __shfl_sync(0xffffffffu, w_l, j);
        float4 v = ((const float4*)(g_h + (size_t)s * 128))[lane];
        acc.x = fmaf(v.x, w, acc.x);
        acc.y = fmaf(v.y, w, acc.y);
        acc.z = fmaf(v.z, w, acc.z);
        acc.w = fmaf(v.w, w, acc.w);
    }
    for (int j = beg + 32; j < beg + deg; j++) {   // rare tail
        int s = g_csrc[j];
        float w = g_dinv[s] * dd;
        float4 v = ((const float4*)(g_h + (size_t)s * 128))[lane];
        acc.x = fmaf(v.x, w, acc.x);
        acc.y = fmaf(v.y, w, acc.y);
        acc.z = fmaf(v.z, w, acc.z);
        acc.w = fmaf(v.w, w, acc.w);
    }
    __stwt(((float4*)(g_agg + (size_t)d * 128)) + lane, acc);
}

// ---------------- column stats ----------------
__global__ void zero_stats() {
    int i = threadIdx.x;
    if (i < 2 * CC) g_stats[i] = 0.f;
}

__global__ void colstats(const float* __restrict__ bias) {
    __shared__ float s1[256], s2[256];
    int c = threadIdx.x & 127;
    int half = threadIdx.x >> 7;
    float b = bias[c];
    float acc = 0.f, acc2 = 0.f;
    for (int r = blockIdx.x * 2 + half; r < NN; r += gridDim.x * 2) {
        float t = g_agg[(size_t)r * 128 + c] + b;
        acc += t;
        acc2 += t * t;
    }
    s1[threadIdx.x] = acc;
    s2[threadIdx.x] = acc2;
    __syncthreads();
    if (half == 0) {
        atomicAdd(&g_stats[c], s1[c] + s1[c + 128]);
        atomicAdd(&g_stats[128 + c], s2[c] + s2[c + 128]);
    }
}

// ---------------- finalize ----------------
template <bool PHASE_B>
__device__ __forceinline__ void finalize_body(const float* __restrict__ xin_ext,
                                              const float* __restrict__ bias,
                                              const float* __restrict__ gw,
                                              const float* __restrict__ gb,
                                              const float* __restrict__ gms,
                                              float* __restrict__ xout_ext) {
    int idx = blockIdx.x * blockDim.x + threadIdx.x;
    if (idx >= NN * CC) return;
    int c = idx & 127;
    float t = g_agg[idx] + bias[c];
    const float invn = 1.0f / (float)NN;
    float mean = g_stats[c] * invn;
    float a = gms[c] * mean;
    float var = g_stats[128 + c] * invn - 2.f * a * mean + a * a;
    float y = gw[c] * (t - a) * rsqrtf(var + EPS_) + gb[c];
    y = (y >= 0.f) ? y : 0.01f * y;
    float xv = PHASE_B ? g_x1[idx] : xin_ext[idx];
    float r = xv + y;
    if (PHASE_B) xout_ext[idx] = r;
    else g_x1[idx] = r;
}

__global__ void finalize_A(const float* __restrict__ xin, const float* __restrict__ bias,
                           const float* __restrict__ gw, const float* __restrict__ gb,
                           const float* __restrict__ gms) {
    finalize_body<false>(xin, bias, gw, gb, gms, nullptr);
}
__global__ void finalize_B(const float* __restrict__ bias, const float* __restrict__ gw,
                           const float* __restrict__ gb, const float* __restrict__ gms,
                           float* __restrict__ xout) {
    finalize_body<true>(nullptr, bias, gw, gb, gms, xout);
}

// ---------------- GAT attention dots ----------------
__global__ void attndot(const float* __restrict__ att_src, const float* __restrict__ att_dst) {
    int warp = (blockIdx.x * blockDim.x + threadIdx.x) >> 5;
    if (warp >= NN) return;
    int lane = threadIdx.x & 31;
    float4 hv = ((const float4*)(g_h + (size_t)warp * 128))[lane];
    float4 av = ((const float4*)att_src)[lane];
    float4 dv = ((const float4*)att_dst)[lane];
    float ps = hv.x * av.x + hv.y * av.y + hv.z * av.z + hv.w * av.w;
    float pd = hv.x * dv.x + hv.y * dv.y + hv.z * dv.z + hv.w * dv.w;
#pragma unroll
    for (int o = 16; o; o >>= 1) {
        ps += __shfl_xor_sync(0xffffffffu, ps, o);
        pd += __shfl_xor_sync(0xffffffffu, pd, o);
    }
    if (lane == 0) {
        g_as[warp] = ps;
        g_ad[warp] = pd;
    }
}

// ---------------- GAT gather (fused softmax, lane-cached) ----------------
__global__ void __launch_bounds__(256) gather_gat() {
    int d = (blockIdx.x * blockDim.x + threadIdx.x) >> 5;
    if (d >= NN) return;
    int lane = threadIdx.x & 31;
    int beg = g_rowstart[d];
    int deg = g_degc[d];
    float add = g_ad[d];
    float es = g_as[d] + add;
    es = (es >= 0.f) ? es : 0.2f * es;

    // lane-cached edges (deg <= 32 fast path covers ~all nodes)
    int s_l = (lane < deg) ? g_csrc[beg + lane] : 0;
    float e_l = -3.4e38f;
    if (lane < deg) {
        float e = g_as[s_l] + add;
        e_l = (e >= 0.f) ? e : 0.2f * e;
    }

    // segment max over cached + tail
    float m = fmaxf(es, e_l);
    for (int j = beg + 32 + lane; j < beg + deg; j += 32) {
        float e = g_as[g_csrc[j]] + add;
        e = (e >= 0.f) ? e : 0.2f * e;
        m = fmaxf(m, e);
    }
#pragma unroll
    for (int o = 16; o; o >>= 1) m = fmaxf(m, __shfl_xor_sync(0xffffffffu, m, o));

    // per-lane exp weight (cached edges), denom
    float ex_l = (lane < deg) ? __expf(e_l - m) : 0.f;
    float part = ex_l;
    for (int j = beg + 32 + lane; j < beg + deg; j += 32) {
        float e = g_as[g_csrc[j]] + add;
        e = (e >= 0.f) ? e : 0.2f * e;
        part += __expf(e - m);
    }
#pragma unroll
    for (int o = 16; o; o >>= 1) part += __shfl_xor_sync(0xffffffffu, part, o);
    float ws = __expf(es - m);
    float rden = 1.0f / (part + ws);

    float4 acc = ((const float4*)(g_h + (size_t)d * 128))[lane];
    acc.x *= ws; acc.y *= ws; acc.z *= ws; acc.w *= ws;
    int n32 = deg < 32 ? deg : 32;
    for (int j = 0; j < n32; j++) {
        int s = __shfl_sync(0xffffffffu, s_l, j);
        float w = __shfl_sync(0xffffffffu, ex_l, j);
        float4 v = ((const float4*)(g_h + (size_t)s * 128))[lane];
        acc.x = fmaf(v.x, w, acc.x);
        acc.y = fmaf(v.y, w, acc.y);
        acc.z = fmaf(v.z, w, acc.z);
        acc.w = fmaf(v.w, w, acc.w);
    }
    for (int j = beg + 32; j < beg + deg; j++) {   // rare tail
        int s = g_csrc[j];
        float e = g_as[s] + add;
        e = (e >= 0.f) ? e : 0.2f * e;
        float w = __expf(e - m);
        float4 v = ((const float4*)(g_h + (size_t)s * 128))[lane];
        acc.x = fmaf(v.x, w, acc.x);
        acc.y = fmaf(v.y, w, acc.y);
        acc.z = fmaf(v.z, w, acc.z);
        acc.w = fmaf(v.w, w, acc.w);
    }
    acc.x *= rden; acc.y *= rden; acc.z *= rden; acc.w *= rden;
    __stwt(((float4*)(g_agg + (size_t)d * 128)) + lane, acc);
}

// ---------------- launch ----------------
extern "C" void kernel_launch(void* const* d_in, const int* in_sizes, int n_in,
                              void* d_out, int out_size) {
    const float* x = (const float*)d_in[0];
    const int* e32 = (const int*)d_in[1];
    const float* W1 = (const float*)d_in[2];
    const float* b1 = (const float*)d_in[3];
    const float* gn_w = (const float*)d_in[4];
    const float* gn_b = (const float*)d_in[5];
    const float* gn_ms = (const float*)d_in[6];
    const float* Wg = (const float*)d_in[7];
    const float* bg = (const float*)d_in[8];
    const float* att_src = (const float*)d_in[9];
    const float* att_dst = (const float*)d_in[10];
    float* out = (float*)d_out;

    const int TPB = 256;
    const int nb_node = NBLK;
    const int nb_edge = (EE + TPB - 1) / TPB;
    const int nb_warp_node = (NN * 32 + TPB - 1) / TPB;
    const int nb_elem = (NN * CC + TPB - 1) / TPB;
    const int gemm_blocks = (NN + 127) / 128;

    // position GEMM at launch #4 so ncu (-s 5 -c 1) profiles it
    detect_dtype<<<1, 256>>>(e32);                 // 1
    zero_counts<<<nb_node, TPB>>>();               // 2
    split_W<<<64, 256>>>(W1);                      // 3
    gemm_tf32_A<<<gemm_blocks, 256>>>(x);          // 4  <-- profiled
    count_deg_kernel<<<nb_edge, TPB>>>(e32);       // 5
    dinv_kernel<<<nb_node, TPB>>>();
    scan1<<<nb_node, 256>>>();
    scan2<<<1, 512>>>();
    scan3<<<nb_node, 256>>>();
    fill_csr<<<nb_edge, TPB>>>(e32);

    // ---- Phase A: GCN ----
    gather_gcn<<<nb_warp_node, TPB>>>();
    zero_stats<<<1, 256>>>();
    colstats<<<512, 256>>>(b1);
    finalize_A<<<nb_elem, TPB>>>(x, b1, gn_w, gn_b, gn_ms);

    // ---- Phase B: GAT ----
    split_W<<<64, 256>>>(Wg);
    gemm_tf32_B<<<gemm_blocks, 256>>>();
    attndot<<<nb_warp_node, TPB>>>(att_src, att_dst);
    gather_gat<<<nb_warp_node, TPB>>>();
    zero_stats<<<1, 256>>>();
    colstats<<<512, 256>>>(bg);
    finalize_B<<<nb_elem, TPB>>>(bg, gn_w, gn_b, gn_ms, out);
}

// round 13
// speedup vs baseline: 1.4999x; 1.0722x over previous
#include <cuda_runtime.h>
#include <cstdint>

#define NN 100000
#define EE 1600000
#define CC 128
#define EPS_ 1e-5f
#define NBLK ((NN + 255) / 256)   // 391

// ---------------- scratch ----------------
__device__ __align__(16) float g_h[(size_t)NN * CC];
__device__ __align__(16) float g_agg[(size_t)NN * CC];
__device__ __align__(16) float g_x1[(size_t)NN * CC];
__device__ float g_dinv[NN];
__device__ float g_as[NN];
__device__ float g_ad[NN];
__device__ float g_stats[2 * CC];
__device__ int g_is64;
__device__ int g_degc[NN];
__device__ int g_rowstart[NN];
__device__ int g_cur[NN];
__device__ int g_bsum[NBLK + 1];
__device__ int g_boff[NBLK + 1];
__device__ int g_csrc[EE];
__device__ __align__(16) unsigned g_Whi[16384];
__device__ __align__(16) unsigned g_Wlo[16384];

// ---------------- edges dtype detection ----------------
__global__ void detect_dtype(const int* __restrict__ e32) {
    __shared__ int ok[256];
    int t = threadIdx.x;
    int all0 = 1;
#pragma unroll
    for (int i = 0; i < 2; i++) {
        int idx = 2 * (t + i * 256) + 1;
        if (e32[idx] != 0) all0 = 0;
    }
    ok[t] = all0;
    __syncthreads();
    for (int s = 128; s; s >>= 1) {
        if (t < s) ok[t] &= ok[t + s];
        __syncthreads();
    }
    if (t == 0) g_is64 = ok[0];
}

__device__ __forceinline__ int edge_src(const int* __restrict__ e32, int t) {
    return g_is64 ? e32[2 * t] : e32[t];
}
__device__ __forceinline__ int edge_dst(const int* __restrict__ e32, int t) {
    return g_is64 ? e32[2 * (EE + t)] : e32[EE + t];
}

// ---------------- CSR build ----------------
__global__ void zero_counts() {
    int i = blockIdx.x * blockDim.x + threadIdx.x;
    if (i < NN) g_degc[i] = 0;
}

__global__ void count_deg_kernel(const int* __restrict__ e32) {
    int t = blockIdx.x * blockDim.x + threadIdx.x;
    if (t < EE) atomicAdd(&g_degc[edge_dst(e32, t)], 1);
}

__global__ void dinv_kernel() {
    int i = blockIdx.x * blockDim.x + threadIdx.x;
    if (i < NN) g_dinv[i] = rsqrtf((float)(g_degc[i] + 1));
}

__global__ void scan1() {
    __shared__ int sm[256];
    int b = blockIdx.x, t = threadIdx.x;
    int idx = b * 256 + t;
    int v = (idx < NN) ? g_degc[idx] : 0;
    sm[t] = v;
    __syncthreads();
    for (int o = 1; o < 256; o <<= 1) {
        int add = (t >= o) ? sm[t - o] : 0;
        __syncthreads();
        sm[t] += add;
        __syncthreads();
    }
    if (idx < NN) g_rowstart[idx] = sm[t] - v;
    if (t == 255) g_bsum[b] = sm[255];
}

__global__ void scan2() {
    __shared__ int sm[512];
    int t = threadIdx.x;
    int v = (t < NBLK) ? g_bsum[t] : 0;
    sm[t] = v;
    __syncthreads();
    for (int o = 1; o < 512; o <<= 1) {
        int add = (t >= o) ? sm[t - o] : 0;
        __syncthreads();
        sm[t] += add;
        __syncthreads();
    }
    if (t < NBLK) g_boff[t] = sm[t] - v;
}

__global__ void scan3() {
    int idx = blockIdx.x * blockDim.x + threadIdx.x;
    if (idx < NN) {
        g_rowstart[idx] += g_boff[blockIdx.x];
        g_cur[idx] = 0;
    }
}

__global__ void fill_csr(const int* __restrict__ e32) {
    int t = blockIdx.x * blockDim.x + threadIdx.x;
    if (t >= EE) return;
    int s = edge_src(e32, t);
    int d = edge_dst(e32, t);
    int pos = g_rowstart[d] + atomicAdd(&g_cur[d], 1);
    g_csrc[pos] = s;
}

// ---------------- TF32 GEMM ----------------
#define MMA_TF32(c, a, b) \
    asm volatile("mma.sync.aligned.m16n8k8.row.col.f32.tf32.tf32.f32 " \
                 "{%0,%1,%2,%3},{%4,%5,%6,%7},{%8,%9},{%0,%1,%2,%3};" \
                 : "+f"((c)[0]), "+f"((c)[1]), "+f"((c)[2]), "+f"((c)[3]) \
                 : "r"((a)[0]), "r"((a)[1]), "r"((a)[2]), "r"((a)[3]), \
                   "r"((b)[0]), "r"((b)[1]))

__device__ __forceinline__ void tf32_split(float v, unsigned& hi, unsigned& lo) {
    asm("cvt.rna.tf32.f32 %0, %1;" : "=r"(hi) : "f"(v));
    float rem = v - __uint_as_float(hi);
    asm("cvt.rna.tf32.f32 %0, %1;" : "=r"(lo) : "f"(rem));
}

__global__ void split_W(const float* __restrict__ W) {
    int slot = blockIdx.x * 256 + threadIdx.x;   // 0..16383
    int rg = slot & 1;
    int lane = (slot >> 1) & 31;
    int nt = (slot >> 6) & 15;
    int kc = slot >> 10;
    int k = kc * 8 + rg * 4 + (lane & 3);
    int n = nt * 8 + (lane >> 2);
    unsigned hi, lo;
    tf32_split(W[k * 128 + n], hi, lo);
    g_Whi[slot] = hi;
    g_Wlo[slot] = lo;
}

// GEMM: smem-staged A (raw floats, padded stride 68 -> conflict-free LDS),
// pre-split W from global, tf32 split in regs. 256 thr = 8 warps (2m x 4n).
template <bool FROM_X1>
__device__ __forceinline__ void gemm_tf32_body(const float* __restrict__ Xext) {
    __shared__ float sX[128 * 68];   // 34.8 KB
    const float* X = FROM_X1 ? g_x1 : Xext;
    int row0 = blockIdx.x * 128;
    int tid = threadIdx.x;
    int w = tid >> 5, lane = tid & 31;
    int wm = w & 1, wn = w >> 1;
    int grp = lane >> 2, four = lane & 3;

    float acc[4][4][4];
#pragma unroll
    for (int mt = 0; mt < 4; mt++)
#pragma unroll
        for (int nt = 0; nt < 4; nt++)
#pragma unroll
            for (int c = 0; c < 4; c++) acc[mt][nt][c] = 0.f;

    int lr_base = wm * 64 + grp;     // local row base within tile

#pragma unroll
    for (int kch = 0; kch < 2; kch++) {
        // stage 128 rows x 64 cols, coalesced float4
#pragma unroll
        for (int i = 0; i < 8; i++) {
            int idx = tid + i * 256;      // 0..2047
            int r = idx >> 4;             // 0..127
            int c4 = idx & 15;            // 0..15
            int gr = row0 + r;
            float4 v = (gr < NN) ? ((const float4*)(X + (size_t)gr * 128 + kch * 64))[c4]
                                 : make_float4(0.f, 0.f, 0.f, 0.f);
            *(float4*)(sX + r * 68 + c4 * 4) = v;
        }
        __syncthreads();

#pragma unroll
        for (int kc2 = 0; kc2 < 8; kc2++) {
            int kc = kch * 8 + kc2;
            unsigned bhi[4][2], blo[4][2];
#pragma unroll
            for (int nt = 0; nt < 4; nt++) {
                int ntg = wn * 4 + nt;
                int base = (kc * 16 + ntg) * 32 + lane;
                *(uint2*)bhi[nt] = ((const uint2*)g_Whi)[base];
                *(uint2*)blo[nt] = ((const uint2*)g_Wlo)[base];
            }
            int colb = kc2 * 8 + four;
#pragma unroll
            for (int mt = 0; mt < 4; mt++) {
                int r0 = lr_base + mt * 16;
                int r1 = r0 + 8;
                float f0 = sX[r0 * 68 + colb];
                float f1 = sX[r1 * 68 + colb];
                float f2 = sX[r0 * 68 + colb + 4];
                float f3 = sX[r1 * 68 + colb + 4];
                unsigned ahi[4], alo[4];
                tf32_split(f0, ahi[0], alo[0]);
                tf32_split(f1, ahi[1], alo[1]);
                tf32_split(f2, ahi[2], alo[2]);
                tf32_split(f3, ahi[3], alo[3]);
#pragma unroll
                for (int nt = 0; nt < 4; nt++) {
                    MMA_TF32(acc[mt][nt], ahi, bhi[nt]);
                    MMA_TF32(acc[mt][nt], alo, bhi[nt]);
                    MMA_TF32(acc[mt][nt], ahi, blo[nt]);
                }
            }
        }
        __syncthreads();
    }

#pragma unroll
    for (int mt = 0; mt < 4; mt++) {
        int r0 = row0 + lr_base + mt * 16;
        int r1 = r0 + 8;
#pragma unroll
        for (int nt = 0; nt < 4; nt++) {
            int coln = wn * 32 + nt * 8 + four * 2;
            if (r0 < NN)
                *(float2*)(g_h + (size_t)r0 * 128 + coln) = make_float2(acc[mt][nt][0], acc[mt][nt][1]);
            if (r1 < NN)
                *(float2*)(g_h + (size_t)r1 * 128 + coln) = make_float2(acc[mt][nt][2], acc[mt][nt][3]);
        }
    }
}

__global__ void __launch_bounds__(256) gemm_tf32_A(const float* __restrict__ X) {
    gemm_tf32_body<false>(X);
}
__global__ void __launch_bounds__(256) gemm_tf32_B() {
    gemm_tf32_body<true>(nullptr);
}

// ---------------- GCN gather: warp per dst, lane-cached edges ----------------
__global__ void __launch_bounds__(256) gather_gcn() {
    int d = (blockIdx.x * blockDim.x + threadIdx.x) >> 5;
    if (d >= NN) return;
    int lane = threadIdx.x & 31;
    int beg = g_rowstart[d];
    int deg = g_degc[d];
    float dd = g_dinv[d];

    int s_l = (lane < deg) ? g_csrc[beg + lane] : 0;
    float w_l = (lane < deg) ? g_dinv[s_l] * dd : 0.f;

    float4 acc = ((const float4*)(g_h + (size_t)d * 128))[lane];
    float w0 = dd * dd;
    acc.x *= w0; acc.y *= w0; acc.z *= w0; acc.w *= w0;

    int n32 = deg < 32 ? deg : 32;
    for (int j = 0; j < n32; j++) {
        int s = __shfl_sync(0xffffffffu, s_l, j);
        float w = __shfl_sync(0xffffffffu, w_l, j);
        float4 v = ((const float4*)(g_h + (size_t)s * 128))[lane];
        acc.x = fmaf(v.x, w, acc.x);
        acc.y = fmaf(v.y, w, acc.y);
        acc.z = fmaf(v.z, w, acc.z);
        acc.w = fmaf(v.w, w, acc.w);
    }
    for (int j = beg + 32; j < beg + deg; j++) {
        int s = g_csrc[j];
        float w = g_dinv[s] * dd;
        float4 v = ((const float4*)(g_h + (size_t)s * 128))[lane];
        acc.x = fmaf(v.x, w, acc.x);
        acc.y = fmaf(v.y, w, acc.y);
        acc.z = fmaf(v.z, w, acc.z);
        acc.w = fmaf(v.w, w, acc.w);
    }
    __stwt(((float4*)(g_agg + (size_t)d * 128)) + lane, acc);
}

// ---------------- column stats ----------------
__global__ void zero_stats() {
    int i = threadIdx.x;
    if (i < 2 * CC) g_stats[i] = 0.f;
}

__global__ void colstats(const float* __restrict__ bias) {
    __shared__ float s1[256], s2[256];
    int c = threadIdx.x & 127;
    int half = threadIdx.x >> 7;
    float b = bias[c];
    float acc = 0.f, acc2 = 0.f;
    for (int r = blockIdx.x * 2 + half; r < NN; r += gridDim.x * 2) {
        float t = g_agg[(size_t)r * 128 + c] + b;
        acc += t;
        acc2 += t * t;
    }
    s1[threadIdx.x] = acc;
    s2[threadIdx.x] = acc2;
    __syncthreads();
    if (half == 0) {
        atomicAdd(&g_stats[c], s1[c] + s1[c + 128]);
        atomicAdd(&g_stats[128 + c], s2[c] + s2[c + 128]);
    }
}

// ---------------- finalize ----------------
template <bool PHASE_B>
__device__ __forceinline__ void finalize_body(const float* __restrict__ xin_ext,
                                              const float* __restrict__ bias,
                                              const float* __restrict__ gw,
                                              const float* __restrict__ gb,
                                              const float* __restrict__ gms,
                                              float* __restrict__ xout_ext) {
    int idx = blockIdx.x * blockDim.x + threadIdx.x;
    if (idx >= NN * CC) return;
    int c = idx & 127;
    float t = g_agg[idx] + bias[c];
    const float invn = 1.0f / (float)NN;
    float mean = g_stats[c] * invn;
    float a = gms[c] * mean;
    float var = g_stats[128 + c] * invn - 2.f * a * mean + a * a;
    float y = gw[c] * (t - a) * rsqrtf(var + EPS_) + gb[c];
    y = (y >= 0.f) ? y : 0.01f * y;
    float xv = PHASE_B ? g_x1[idx] : xin_ext[idx];
    float r = xv + y;
    if (PHASE_B) xout_ext[idx] = r;
    else g_x1[idx] = r;
}

__global__ void finalize_A(const float* __restrict__ xin, const float* __restrict__ bias,
                           const float* __restrict__ gw, const float* __restrict__ gb,
                           const float* __restrict__ gms) {
    finalize_body<false>(xin, bias, gw, gb, gms, nullptr);
}
__global__ void finalize_B(const float* __restrict__ bias, const float* __restrict__ gw,
                           const float* __restrict__ gb, const float* __restrict__ gms,
                           float* __restrict__ xout) {
    finalize_body<true>(nullptr, bias, gw, gb, gms, xout);
}

// ---------------- GAT attention dots ----------------
__global__ void attndot(const float* __restrict__ att_src, const float* __restrict__ att_dst) {
    int warp = (blockIdx.x * blockDim.x + threadIdx.x) >> 5;
    if (warp >= NN) return;
    int lane = threadIdx.x & 31;
    float4 hv = ((const float4*)(g_h + (size_t)warp * 128))[lane];
    float4 av = ((const float4*)att_src)[lane];
    float4 dv = ((const float4*)att_dst)[lane];
    float ps = hv.x * av.x + hv.y * av.y + hv.z * av.z + hv.w * av.w;
    float pd = hv.x * dv.x + hv.y * dv.y + hv.z * dv.z + hv.w * dv.w;
#pragma unroll
    for (int o = 16; o; o >>= 1) {
        ps += __shfl_xor_sync(0xffffffffu, ps, o);
        pd += __shfl_xor_sync(0xffffffffu, pd, o);
    }
    if (lane == 0) {
        g_as[warp] = ps;
        g_ad[warp] = pd;
    }
}

// ---------------- GAT gather (fused softmax, lane-cached) ----------------
__global__ void __launch_bounds__(256) gather_gat() {
    int d = (blockIdx.x * blockDim.x + threadIdx.x) >> 5;
    if (d >= NN) return;
    int lane = threadIdx.x & 31;
    int beg = g_rowstart[d];
    int deg = g_degc[d];
    float add = g_ad[d];
    float es = g_as[d] + add;
    es = (es >= 0.f) ? es : 0.2f * es;

    int s_l = (lane < deg) ? g_csrc[beg + lane] : 0;
    float e_l = -3.4e38f;
    if (lane < deg) {
        float e = g_as[s_l] + add;
        e_l = (e >= 0.f) ? e : 0.2f * e;
    }

    float m = fmaxf(es, e_l);
    for (int j = beg + 32 + lane; j < beg + deg; j += 32) {
        float e = g_as[g_csrc[j]] + add;
        e = (e >= 0.f) ? e : 0.2f * e;
        m = fmaxf(m, e);
    }
#pragma unroll
    for (int o = 16; o; o >>= 1) m = fmaxf(m, __shfl_xor_sync(0xffffffffu, m, o));

    float ex_l = (lane < deg) ? __expf(e_l - m) : 0.f;
    float part = ex_l;
    for (int j = beg + 32 + lane; j < beg + deg; j += 32) {
        float e = g_as[g_csrc[j]] + add;
        e = (e >= 0.f) ? e : 0.2f * e;
        part += __expf(e - m);
    }
#pragma unroll
    for (int o = 16; o; o >>= 1) part += __shfl_xor_sync(0xffffffffu, part, o);
    float ws = __expf(es - m);
    float rden = 1.0f / (part + ws);

    float4 acc = ((const float4*)(g_h + (size_t)d * 128))[lane];
    acc.x *= ws; acc.y *= ws; acc.z *= ws; acc.w *= ws;
    int n32 = deg < 32 ? deg : 32;
    for (int j = 0; j < n32; j++) {
        int s = __shfl_sync(0xffffffffu, s_l, j);
        float w = __shfl_sync(0xffffffffu, ex_l, j);
        float4 v = ((const float4*)(g_h + (size_t)s * 128))[lane];
        acc.x = fmaf(v.x, w, acc.x);
        acc.y = fmaf(v.y, w, acc.y);
        acc.z = fmaf(v.z, w, acc.z);
        acc.w = fmaf(v.w, w, acc.w);
    }
    for (int j = beg + 32; j < beg + deg; j++) {
        int s = g_csrc[j];
        float e = g_as[s] + add;
        e = (e >= 0.f) ? e : 0.2f * e;
        float w = __expf(e - m);
        float4 v = ((const float4*)(g_h + (size_t)s * 128))[lane];
        acc.x = fmaf(v.x, w, acc.x);
        acc.y = fmaf(v.y, w, acc.y);
        acc.z = fmaf(v.z, w, acc.z);
        acc.w = fmaf(v.w, w, acc.w);
    }
    acc.x *= rden; acc.y *= rden; acc.z *= rden; acc.w *= rden;
    __stwt(((float4*)(g_agg + (size_t)d * 128)) + lane, acc);
}

// ---------------- launch ----------------
extern "C" void kernel_launch(void* const* d_in, const int* in_sizes, int n_in,
                              void* d_out, int out_size) {
    const float* x = (const float*)d_in[0];
    const int* e32 = (const int*)d_in[1];
    const float* W1 = (const float*)d_in[2];
    const float* b1 = (const float*)d_in[3];
    const float* gn_w = (const float*)d_in[4];
    const float* gn_b = (const float*)d_in[5];
    const float* gn_ms = (const float*)d_in[6];
    const float* Wg = (const float*)d_in[7];
    const float* bg = (const float*)d_in[8];
    const float* att_src = (const float*)d_in[9];
    const float* att_dst = (const float*)d_in[10];
    float* out = (float*)d_out;

    const int TPB = 256;
    const int nb_node = NBLK;
    const int nb_edge = (EE + TPB - 1) / TPB;
    const int nb_warp_node = (NN * 32 + TPB - 1) / TPB;
    const int nb_elem = (NN * CC + TPB - 1) / TPB;
    const int gemm_blocks = (NN + 127) / 128;

    // position GEMM at launch #4 so ncu (-s 5 -c 1) profiles it
    detect_dtype<<<1, 256>>>(e32);                 // 1
    zero_counts<<<nb_node, TPB>>>();               // 2
    split_W<<<64, 256>>>(W1);                      // 3
    gemm_tf32_A<<<gemm_blocks, 256>>>(x);          // 4  <-- profiled
    count_deg_kernel<<<nb_edge, TPB>>>(e32);       // 5
    dinv_kernel<<<nb_node, TPB>>>();
    scan1<<<nb_node, 256>>>();
    scan2<<<1, 512>>>();
    scan3<<<nb_node, 256>>>();
    fill_csr<<<nb_edge, TPB>>>(e32);

    // ---- Phase A: GCN ----
    gather_gcn<<<nb_warp_node, TPB>>>();
    zero_stats<<<1, 256>>>();
    colstats<<<512, 256>>>(b1);
    finalize_A<<<nb_elem, TPB>>>(x, b1, gn_w, gn_b, gn_ms);

    // ---- Phase B: GAT ----
    split_W<<<64, 256>>>(Wg);
    gemm_tf32_B<<<gemm_blocks, 256>>>();
    attndot<<<nb_warp_node, TPB>>>(att_src, att_dst);
    gather_gat<<<nb_warp_node, TPB>>>();
    zero_stats<<<1, 256>>>();
    colstats<<<512, 256>>>(bg);
    finalize_B<<<nb_elem, TPB>>>(bg, gn_w, gn_b, gn_ms, out);
}

// round 14
// speedup vs baseline: 1.6207x; 1.0806x over previous
#include <cuda_runtime.h>
#include <cstdint>

#define NN 100000
#define EE 1600000
#define CC 128
#define EPS_ 1e-5f
#define NBLK ((NN + 255) / 256)   // 391

// ---------------- scratch ----------------
__device__ __align__(16) float g_h[(size_t)NN * CC];
__device__ __align__(16) float g_agg[(size_t)NN * CC];
__device__ __align__(16) float g_x1[(size_t)NN * CC];
__device__ float g_dinv[NN];
__device__ float g_as[NN];
__device__ float g_ad[NN];
__device__ float g_stats[2 * CC];
__device__ int g_is64;
__device__ int g_degc[NN];
__device__ int g_rowstart[NN];
__device__ int g_cur[NN];
__device__ int g_bsum[NBLK + 1];
__device__ int g_boff[NBLK + 1];
__device__ int g_csrc[EE];
__device__ __align__(16) unsigned g_Whi[16384];
__device__ __align__(16) unsigned g_Wlo[16384];

// ---------------- edges dtype detection ----------------
__global__ void detect_dtype(const int* __restrict__ e32) {
    __shared__ int ok[256];
    int t = threadIdx.x;
    int all0 = 1;
#pragma unroll
    for (int i = 0; i < 2; i++) {
        int idx = 2 * (t + i * 256) + 1;
        if (e32[idx] != 0) all0 = 0;
    }
    ok[t] = all0;
    __syncthreads();
    for (int s = 128; s; s >>= 1) {
        if (t < s) ok[t] &= ok[t + s];
        __syncthreads();
    }
    if (t == 0) g_is64 = ok[0];
}

__device__ __forceinline__ int edge_src(const int* __restrict__ e32, int t) {
    return g_is64 ? e32[2 * t] : e32[t];
}
__device__ __forceinline__ int edge_dst(const int* __restrict__ e32, int t) {
    return g_is64 ? e32[2 * (EE + t)] : e32[EE + t];
}

// ---------------- CSR build ----------------
__global__ void zero_counts() {
    int i = blockIdx.x * blockDim.x + threadIdx.x;
    if (i < NN) g_degc[i] = 0;
}

__global__ void count_deg_kernel(const int* __restrict__ e32) {
    int t = blockIdx.x * blockDim.x + threadIdx.x;
    if (t < EE) atomicAdd(&g_degc[edge_dst(e32, t)], 1);
}

__global__ void dinv_kernel() {
    int i = blockIdx.x * blockDim.x + threadIdx.x;
    if (i < NN) g_dinv[i] = rsqrtf((float)(g_degc[i] + 1));
}

__global__ void scan1() {
    __shared__ int sm[256];
    int b = blockIdx.x, t = threadIdx.x;
    int idx = b * 256 + t;
    int v = (idx < NN) ? g_degc[idx] : 0;
    sm[t] = v;
    __syncthreads();
    for (int o = 1; o < 256; o <<= 1) {
        int add = (t >= o) ? sm[t - o] : 0;
        __syncthreads();
        sm[t] += add;
        __syncthreads();
    }
    if (idx < NN) g_rowstart[idx] = sm[t] - v;
    if (t == 255) g_bsum[b] = sm[255];
}

__global__ void scan2() {
    __shared__ int sm[512];
    int t = threadIdx.x;
    int v = (t < NBLK) ? g_bsum[t] : 0;
    sm[t] = v;
    __syncthreads();
    for (int o = 1; o < 512; o <<= 1) {
        int add = (t >= o) ? sm[t - o] : 0;
        __syncthreads();
        sm[t] += add;
        __syncthreads();
    }
    if (t < NBLK) g_boff[t] = sm[t] - v;
}

__global__ void scan3() {
    int idx = blockIdx.x * blockDim.x + threadIdx.x;
    if (idx < NN) {
        g_rowstart[idx] += g_boff[blockIdx.x];
        g_cur[idx] = 0;
    }
}

__global__ void fill_csr(const int* __restrict__ e32) {
    int t = blockIdx.x * blockDim.x + threadIdx.x;
    if (t >= EE) return;
    int s = edge_src(e32, t);
    int d = edge_dst(e32, t);
    int pos = g_rowstart[d] + atomicAdd(&g_cur[d], 1);
    g_csrc[pos] = s;
}

// ---------------- TF32 GEMM ----------------
#define MMA_TF32(c, a, b) \
    asm volatile("mma.sync.aligned.m16n8k8.row.col.f32.tf32.tf32.f32 " \
                 "{%0,%1,%2,%3},{%4,%5,%6,%7},{%8,%9},{%0,%1,%2,%3};" \
                 : "+f"((c)[0]), "+f"((c)[1]), "+f"((c)[2]), "+f"((c)[3]) \
                 : "r"((a)[0]), "r"((a)[1]), "r"((a)[2]), "r"((a)[3]), \
                   "r"((b)[0]), "r"((b)[1]))

__device__ __forceinline__ void tf32_split(float v, unsigned& hi, unsigned& lo) {
    asm("cvt.rna.tf32.f32 %0, %1;" : "=r"(hi) : "f"(v));
    float rem = v - __uint_as_float(hi);
    asm("cvt.rna.tf32.f32 %0, %1;" : "=r"(lo) : "f"(rem));
}

__global__ void split_W(const float* __restrict__ W) {
    int slot = blockIdx.x * 256 + threadIdx.x;   // 0..16383
    int rg = slot & 1;
    int lane = (slot >> 1) & 31;
    int nt = (slot >> 6) & 15;
    int kc = slot >> 10;
    int k = kc * 8 + rg * 4 + (lane & 3);
    int n = nt * 8 + (lane >> 2);
    unsigned hi, lo;
    tf32_split(W[k * 128 + n], hi, lo);
    g_Whi[slot] = hi;
    g_Wlo[slot] = lo;
}

// GEMM: 64-row tile, smem-staged A, pre-split W, 256 thr = 8 warps (2m x 4n),
// mt=2 -> 32 acc regs -> 2 CTAs/SM (16 warps) for latency hiding.
template <bool FROM_X1>
__device__ __forceinline__ void gemm_tf32_body(const float* __restrict__ Xext) {
    __shared__ float sX[64 * 68];   // 17.4 KB
    const float* X = FROM_X1 ? g_x1 : Xext;
    int row0 = blockIdx.x * 64;
    int tid = threadIdx.x;
    int w = tid >> 5, lane = tid & 31;
    int wm = w & 1, wn = w >> 1;
    int grp = lane >> 2, four = lane & 3;

    float acc[2][4][4];
#pragma unroll
    for (int mt = 0; mt < 2; mt++)
#pragma unroll
        for (int nt = 0; nt < 4; nt++)
#pragma unroll
            for (int c = 0; c < 4; c++) acc[mt][nt][c] = 0.f;

    int lr_base = wm * 32 + grp;

#pragma unroll
    for (int kch = 0; kch < 2; kch++) {
        // stage 64 rows x 64 cols, coalesced float4
#pragma unroll
        for (int i = 0; i < 4; i++) {
            int idx = tid + i * 256;      // 0..1023
            int r = idx >> 4;             // 0..63
            int c4 = idx & 15;            // 0..15
            int gr = row0 + r;
            float4 v = (gr < NN) ? ((const float4*)(X + (size_t)gr * 128 + kch * 64))[c4]
                                 : make_float4(0.f, 0.f, 0.f, 0.f);
            *(float4*)(sX + r * 68 + c4 * 4) = v;
        }
        __syncthreads();

#pragma unroll
        for (int kc2 = 0; kc2 < 8; kc2++) {
            int kc = kch * 8 + kc2;
            unsigned bhi[4][2], blo[4][2];
#pragma unroll
            for (int nt = 0; nt < 4; nt++) {
                int ntg = wn * 4 + nt;
                int base = (kc * 16 + ntg) * 32 + lane;
                *(uint2*)bhi[nt] = ((const uint2*)g_Whi)[base];
                *(uint2*)blo[nt] = ((const uint2*)g_Wlo)[base];
            }
            int colb = kc2 * 8 + four;
#pragma unroll
            for (int mt = 0; mt < 2; mt++) {
                int r0 = lr_base + mt * 16;
                int r1 = r0 + 8;
                float f0 = sX[r0 * 68 + colb];
                float f1 = sX[r1 * 68 + colb];
                float f2 = sX[r0 * 68 + colb + 4];
                float f3 = sX[r1 * 68 + colb + 4];
                unsigned ahi[4], alo[4];
                tf32_split(f0, ahi[0], alo[0]);
                tf32_split(f1, ahi[1], alo[1]);
                tf32_split(f2, ahi[2], alo[2]);
                tf32_split(f3, ahi[3], alo[3]);
#pragma unroll
                for (int nt = 0; nt < 4; nt++) {
                    MMA_TF32(acc[mt][nt], ahi, bhi[nt]);
                    MMA_TF32(acc[mt][nt], alo, bhi[nt]);
                    MMA_TF32(acc[mt][nt], ahi, blo[nt]);
                }
            }
        }
        __syncthreads();
    }

#pragma unroll
    for (int mt = 0; mt < 2; mt++) {
        int r0 = row0 + lr_base + mt * 16;
        int r1 = r0 + 8;
#pragma unroll
        for (int nt = 0; nt < 4; nt++) {
            int coln = wn * 32 + nt * 8 + four * 2;
            if (r0 < NN)
                *(float2*)(g_h + (size_t)r0 * 128 + coln) = make_float2(acc[mt][nt][0], acc[mt][nt][1]);
            if (r1 < NN)
                *(float2*)(g_h + (size_t)r1 * 128 + coln) = make_float2(acc[mt][nt][2], acc[mt][nt][3]);
        }
    }
}

__global__ void __launch_bounds__(256, 2) gemm_tf32_A(const float* __restrict__ X) {
    gemm_tf32_body<false>(X);
}
__global__ void __launch_bounds__(256, 2) gemm_tf32_B() {
    gemm_tf32_body<true>(nullptr);
}

// ---------------- GCN gather: warp per dst, lane-cached edges ----------------
__global__ void __launch_bounds__(256) gather_gcn() {
    int d = (blockIdx.x * blockDim.x + threadIdx.x) >> 5;
    if (d >= NN) return;
    int lane = threadIdx.x & 31;
    int beg = g_rowstart[d];
    int deg = g_degc[d];
    float dd = g_dinv[d];

    int s_l = (lane < deg) ? g_csrc[beg + lane] : 0;
    float w_l = (lane < deg) ? g_dinv[s_l] * dd : 0.f;

    float4 acc = ((const float4*)(g_h + (size_t)d * 128))[lane];
    float w0 = dd * dd;
    acc.x *= w0; acc.y *= w0; acc.z *= w0; acc.w *= w0;

    int n32 = deg < 32 ? deg : 32;
    for (int j = 0; j < n32; j++) {
        int s = __shfl_sync(0xffffffffu, s_l, j);
        float w = __shfl_sync(0xffffffffu, w_l, j);
        float4 v = ((const float4*)(g_h + (size_t)s * 128))[lane];
        acc.x = fmaf(v.x, w, acc.x);
        acc.y = fmaf(v.y, w, acc.y);
        acc.z = fmaf(v.z, w, acc.z);
        acc.w = fmaf(v.w, w, acc.w);
    }
    for (int j = beg + 32; j < beg + deg; j++) {
        int s = g_csrc[j];
        float w = g_dinv[s] * dd;
        float4 v = ((const float4*)(g_h + (size_t)s * 128))[lane];
        acc.x = fmaf(v.x, w, acc.x);
        acc.y = fmaf(v.y, w, acc.y);
        acc.z = fmaf(v.z, w, acc.z);
        acc.w = fmaf(v.w, w, acc.w);
    }
    __stwt(((float4*)(g_agg + (size_t)d * 128)) + lane, acc);
}

// ---------------- column stats ----------------
__global__ void zero_stats() {
    int i = threadIdx.x;
    if (i < 2 * CC) g_stats[i] = 0.f;
}

__global__ void colstats(const float* __restrict__ bias) {
    __shared__ float s1[256], s2[256];
    int c = threadIdx.x & 127;
    int half = threadIdx.x >> 7;
    float b = bias[c];
    float acc = 0.f, acc2 = 0.f;
    for (int r = blockIdx.x * 2 + half; r < NN; r += gridDim.x * 2) {
        float t = g_agg[(size_t)r * 128 + c] + b;
        acc += t;
        acc2 += t * t;
    }
    s1[threadIdx.x] = acc;
    s2[threadIdx.x] = acc2;
    __syncthreads();
    if (half == 0) {
        atomicAdd(&g_stats[c], s1[c] + s1[c + 128]);
        atomicAdd(&g_stats[128 + c], s2[c] + s2[c + 128]);
    }
}

// ---------------- finalize ----------------
template <bool PHASE_B>
__device__ __forceinline__ void finalize_body(const float* __restrict__ xin_ext,
                                              const float* __restrict__ bias,
                                              const float* __restrict__ gw,
                                              const float* __restrict__ gb,
                                              const float* __restrict__ gms,
                                              float* __restrict__ xout_ext) {
    int idx = blockIdx.x * blockDim.x + threadIdx.x;
    if (idx >= NN * CC) return;
    int c = idx & 127;
    float t = g_agg[idx] + bias[c];
    const float invn = 1.0f / (float)NN;
    float mean = g_stats[c] * invn;
    float a = gms[c] * mean;
    float var = g_stats[128 + c] * invn - 2.f * a * mean + a * a;
    float y = gw[c] * (t - a) * rsqrtf(var + EPS_) + gb[c];
    y = (y >= 0.f) ? y : 0.01f * y;
    float xv = PHASE_B ? g_x1[idx] : xin_ext[idx];
    float r = xv + y;
    if (PHASE_B) xout_ext[idx] = r;
    else g_x1[idx] = r;
}

__global__ void finalize_A(const float* __restrict__ xin, const float* __restrict__ bias,
                           const float* __restrict__ gw, const float* __restrict__ gb,
                           const float* __restrict__ gms) {
    finalize_body<false>(xin, bias, gw, gb, gms, nullptr);
}
__global__ void finalize_B(const float* __restrict__ bias, const float* __restrict__ gw,
                           const float* __restrict__ gb, const float* __restrict__ gms,
                           float* __restrict__ xout) {
    finalize_body<true>(nullptr, bias, gw, gb, gms, xout);
}

// ---------------- GAT attention dots ----------------
__global__ void attndot(const float* __restrict__ att_src, const float* __restrict__ att_dst) {
    int warp = (blockIdx.x * blockDim.x + threadIdx.x) >> 5;
    if (warp >= NN) return;
    int lane = threadIdx.x & 31;
    float4 hv = ((const float4*)(g_h + (size_t)warp * 128))[lane];
    float4 av = ((const float4*)att_src)[lane];
    float4 dv = ((const float4*)att_dst)[lane];
    float ps = hv.x * av.x + hv.y * av.y + hv.z * av.z + hv.w * av.w;
    float pd = hv.x * dv.x + hv.y * dv.y + hv.z * dv.z + hv.w * dv.w;
#pragma unroll
    for (int o = 16; o; o >>= 1) {
        ps += __shfl_xor_sync(0xffffffffu, ps, o);
        pd += __shfl_xor_sync(0xffffffffu, pd, o);
    }
    if (lane == 0) {
        g_as[warp] = ps;
        g_ad[warp] = pd;
    }
}

// ---------------- GAT gather (fused softmax, lane-cached) ----------------
__global__ void __launch_bounds__(256) gather_gat() {
    int d = (blockIdx.x * blockDim.x + threadIdx.x) >> 5;
    if (d >= NN) return;
    int lane = threadIdx.x & 31;
    int beg = g_rowstart[d];
    int deg = g_degc[d];
    float add = g_ad[d];
    float es = g_as[d] + add;
    es = (es >= 0.f) ? es : 0.2f * es;

    int s_l = (lane < deg) ? g_csrc[beg + lane] : 0;
    float e_l = -3.4e38f;
    if (lane < deg) {
        float e = g_as[s_l] + add;
        e_l = (e >= 0.f) ? e : 0.2f * e;
    }

    float m = fmaxf(es, e_l);
    for (int j = beg + 32 + lane; j < beg + deg; j += 32) {
        float e = g_as[g_csrc[j]] + add;
        e = (e >= 0.f) ? e : 0.2f * e;
        m = fmaxf(m, e);
    }
#pragma unroll
    for (int o = 16; o; o >>= 1) m = fmaxf(m, __shfl_xor_sync(0xffffffffu, m, o));

    float ex_l = (lane < deg) ? __expf(e_l - m) : 0.f;
    float part = ex_l;
    for (int j = beg + 32 + lane; j < beg + deg; j += 32) {
        float e = g_as[g_csrc[j]] + add;
        e = (e >= 0.f) ? e : 0.2f * e;
        part += __expf(e - m);
    }
#pragma unroll
    for (int o = 16; o; o >>= 1) part += __shfl_xor_sync(0xffffffffu, part, o);
    float ws = __expf(es - m);
    float rden = 1.0f / (part + ws);

    float4 acc = ((const float4*)(g_h + (size_t)d * 128))[lane];
    acc.x *= ws; acc.y *= ws; acc.z *= ws; acc.w *= ws;
    int n32 = deg < 32 ? deg : 32;
    for (int j = 0; j < n32; j++) {
        int s = __shfl_sync(0xffffffffu, s_l, j);
        float w = __shfl_sync(0xffffffffu, ex_l, j);
        float4 v = ((const float4*)(g_h + (size_t)s * 128))[lane];
        acc.x = fmaf(v.x, w, acc.x);
        acc.y = fmaf(v.y, w, acc.y);
        acc.z = fmaf(v.z, w, acc.z);
        acc.w = fmaf(v.w, w, acc.w);
    }
    for (int j = beg + 32; j < beg + deg; j++) {
        int s = g_csrc[j];
        float e = g_as[s] + add;
        e = (e >= 0.f) ? e : 0.2f * e;
        float w = __expf(e - m);
        float4 v = ((const float4*)(g_h + (size_t)s * 128))[lane];
        acc.x = fmaf(v.x, w, acc.x);
        acc.y = fmaf(v.y, w, acc.y);
        acc.z = fmaf(v.z, w, acc.z);
        acc.w = fmaf(v.w, w, acc.w);
    }
    acc.x *= rden; acc.y *= rden; acc.z *= rden; acc.w *= rden;
    __stwt(((float4*)(g_agg + (size_t)d * 128)) + lane, acc);
}

// ---------------- launch ----------------
extern "C" void kernel_launch(void* const* d_in, const int* in_sizes, int n_in,
                              void* d_out, int out_size) {
    const float* x = (const float*)d_in[0];
    const int* e32 = (const int*)d_in[1];
    const float* W1 = (const float*)d_in[2];
    const float* b1 = (const float*)d_in[3];
    const float* gn_w = (const float*)d_in[4];
    const float* gn_b = (const float*)d_in[5];
    const float* gn_ms = (const float*)d_in[6];
    const float* Wg = (const float*)d_in[7];
    const float* bg = (const float*)d_in[8];
    const float* att_src = (const float*)d_in[9];
    const float* att_dst = (const float*)d_in[10];
    float* out = (float*)d_out;

    const int TPB = 256;
    const int nb_node = NBLK;
    const int nb_edge = (EE + TPB - 1) / TPB;
    const int nb_warp_node = (NN * 32 + TPB - 1) / TPB;
    const int nb_elem = (NN * CC + TPB - 1) / TPB;
    const int gemm_blocks = (NN + 63) / 64;

    // position GEMM at launch #4 so ncu (-s 5 -c 1) profiles it
    detect_dtype<<<1, 256>>>(e32);                 // 1
    zero_counts<<<nb_node, TPB>>>();               // 2
    split_W<<<64, 256>>>(W1);                      // 3
    gemm_tf32_A<<<gemm_blocks, 256>>>(x);          // 4  <-- profiled
    count_deg_kernel<<<nb_edge, TPB>>>(e32);       // 5
    dinv_kernel<<<nb_node, TPB>>>();
    scan1<<<nb_node, 256>>>();
    scan2<<<1, 512>>>();
    scan3<<<nb_node, 256>>>();
    fill_csr<<<nb_edge, TPB>>>(e32);

    // ---- Phase A: GCN ----
    gather_gcn<<<nb_warp_node, TPB>>>();
    zero_stats<<<1, 256>>>();
    colstats<<<512, 256>>>(b1);
    finalize_A<<<nb_elem, TPB>>>(x, b1, gn_w, gn_b, gn_ms);

    // ---- Phase B: GAT ----
    split_W<<<64, 256>>>(Wg);
    gemm_tf32_B<<<gemm_blocks, 256>>>();
    attndot<<<nb_warp_node, TPB>>>(att_src, att_dst);
    gather_gat<<<nb_warp_node, TPB>>>();
    zero_stats<<<1, 256>>>();
    colstats<<<512, 256>>>(bg);
    finalize_B<<<nb_elem, TPB>>>(bg, gn_w, gn_b, gn_ms, out);
}